// round 6
// baseline (speedup 1.0000x reference)
#include <cuda_runtime.h>
#include <cstdint>

// Shapes fixed by problem: N=1024 nodes, D=256 feat, H=256 hidden.
#define NN 1024
#define DD 256
#define HH 256
#define NBLK 128          // 16 clusters x 8 CTAs
#define NTHR 512          // 16 warps/CTA
#define CSZ 8             // cluster size

__device__ __forceinline__ float warp_reduce(float v) {
#pragma unroll
    for (int o = 16; o > 0; o >>= 1) v += __shfl_xor_sync(0xffffffffu, v, o);
    return v;
}

__device__ __forceinline__ float frcp(float x) {
    float y;
    asm("rcp.approx.f32 %0, %1;" : "=f"(y) : "f"(x));
    return y;
}

__device__ __forceinline__ uint32_t cluster_rank() {
    uint32_t r;
    asm("mov.u32 %0, %%cluster_ctarank;" : "=r"(r));
    return r;
}

__device__ __forceinline__ void cluster_arrive() {
    asm volatile("barrier.cluster.arrive.aligned;" ::: "memory");
}
__device__ __forceinline__ void cluster_wait() {
    asm volatile("barrier.cluster.wait.aligned;" ::: "memory");
}

// Read a float from a peer CTA's shared memory (same smem offset, given rank).
__device__ __forceinline__ float dsmem_read_f32(uint32_t local_addr, uint32_t rank) {
    uint32_t remote;
    asm("mapa.shared::cluster.u32 %0, %1, %2;" : "=r"(remote) : "r"(local_addr), "r"(rank));
    float v;
    asm volatile("ld.shared::cluster.f32 %0, [%1];" : "=f"(v) : "r"(remote));
    return v;
}

__device__ __forceinline__ float dot256(const float4* __restrict__ row,
                                        float4 a0, float4 a1, int lane) {
    float4 r0 = row[lane];
    float4 r1 = row[lane + 32];
    float acc = r0.x * a0.x;
    acc = fmaf(r0.y, a0.y, acc);
    acc = fmaf(r0.z, a0.z, acc);
    acc = fmaf(r0.w, a0.w, acc);
    acc = fmaf(r1.x, a1.x, acc);
    acc = fmaf(r1.y, a1.y, acc);
    acc = fmaf(r1.z, a1.z, acc);
    acc = fmaf(r1.w, a1.w, acc);
    return warp_reduce(acc);
}

__global__ void __launch_bounds__(NTHR, 1) __cluster_dims__(CSZ, 1, 1)
fused_decoder(const float* __restrict__ z,  const float* __restrict__ w1,
              const float* __restrict__ b1, const float* __restrict__ w2,
              const float* __restrict__ b2, float* __restrict__ out) {
    // Per-CTA shared state, 16B-aligned (read as float4 / LDS.128).
    __shared__ __align__(16) float s_chunk[64];   // this rank's 64 p-or-q values
    __shared__ __align__(16) float s_eul[128];    // this rank's 128 eu values
    __shared__ __align__(16) float s_evl[128];    // this rank's 128 ev values
    __shared__ __align__(16) float s_p[DD];       // assembled p
    __shared__ __align__(16) float s_q[DD];       // assembled q
    __shared__ __align__(16) float s_eu[NN];      // assembled eu (all nodes)
    __shared__ __align__(16) float s_ev[NN];      // assembled ev (all nodes)
    __shared__ float s_cslot;                     // rank 0: c = b1.w2 + b2
    __shared__ float s_c;

    const int t    = threadIdx.x;
    const int lane = t & 31;
    const int wid  = t >> 5;             // 0..15
    const uint32_t rank = cluster_rank();

    const uint32_t a_chunk = (uint32_t)__cvta_generic_to_shared(s_chunk);
    const uint32_t a_cslot = (uint32_t)__cvta_generic_to_shared(&s_cslot);
    const uint32_t a_eul   = (uint32_t)__cvta_generic_to_shared(s_eul);
    const uint32_t a_evl   = (uint32_t)__cvta_generic_to_shared(s_evl);

    // ---- Phase A: this rank computes w1 rows [rank*64, rank*64+64) dotted with w2 ----
    {
        const float4* w2v = reinterpret_cast<const float4*>(w2);
        const float4 a0 = w2v[lane];
        const float4 a1 = w2v[lane + 32];
#pragma unroll
        for (int k = 0; k < 4; k++) {
            const int li = wid * 4 + k;                        // 0..63
            const int g  = (int)rank * 64 + li;                // w1 row 0..511
            const float4* row = reinterpret_cast<const float4*>(w1 + (size_t)g * HH);
            float acc = dot256(row, a0, a1, lane);
            if (lane == 0) s_chunk[li] = acc;
        }
        if (rank == 0 && wid == 0) {                           // c = b1.w2 + b2
            const float4* rb = reinterpret_cast<const float4*>(b1);
            float acc = dot256(rb, a0, a1, lane);
            if (lane == 0) s_cslot = acc + b2[0];
        }
    }

    cluster_arrive();   // release smem writes to cluster
    cluster_wait();     // acquire peers' phase-A writes

    // ---- Assemble full p,q (+c) from peer smem ----
    if (t < 256) {
        s_p[t] = dsmem_read_f32(a_chunk + (uint32_t)(t & 63) * 4u, (uint32_t)(t >> 6));
    } else {
        int u = t - 256;
        s_q[u] = dsmem_read_f32(a_chunk + (uint32_t)(u & 63) * 4u, (uint32_t)(u >> 6) + 4u);
    }
    if (t == 0) s_c = dsmem_read_f32(a_cslot, 0u);
    __syncthreads();

    // ---- Phase B: this rank computes eu/ev for nodes [rank*128, rank*128+128) ----
    {
        const float4* pv = reinterpret_cast<const float4*>(s_p);
        const float4* qv = reinterpret_cast<const float4*>(s_q);
        const float4 p0 = pv[lane], p1 = pv[lane + 32];
        const float4 q0 = qv[lane], q1 = qv[lane + 32];
        const float c = s_c;
#pragma unroll
        for (int k = 0; k < 8; k++) {
            const int li = wid * 8 + k;                        // 0..127
            const int n  = (int)rank * 128 + li;               // node 0..1023
            const float4* row = reinterpret_cast<const float4*>(z + (size_t)n * DD);
            float4 z0 = row[lane];
            float4 z1 = row[lane + 32];
            float su = z0.x * p0.x;
            su = fmaf(z0.y, p0.y, su);
            su = fmaf(z0.z, p0.z, su);
            su = fmaf(z0.w, p0.w, su);
            su = fmaf(z1.x, p1.x, su);
            su = fmaf(z1.y, p1.y, su);
            su = fmaf(z1.z, p1.z, su);
            su = fmaf(z1.w, p1.w, su);
            float sv = z0.x * q0.x;
            sv = fmaf(z0.y, q0.y, sv);
            sv = fmaf(z0.z, q0.z, sv);
            sv = fmaf(z0.w, q0.w, sv);
            sv = fmaf(z1.x, q1.x, sv);
            sv = fmaf(z1.y, q1.y, sv);
            sv = fmaf(z1.z, q1.z, sv);
            sv = fmaf(z1.w, q1.w, sv);
            su = warp_reduce(su);
            sv = warp_reduce(sv);
            if (lane == 0) {
                s_eul[li] = __expf(-(su + c));
                s_evl[li] = __expf(-sv);
            }
        }
    }

    cluster_arrive();
    cluster_wait();

    // ---- Assemble full eu/ev from peer smem (4 remote reads per thread) ----
    {
        const uint32_t off = (uint32_t)(t & 127) * 4u;
        const uint32_t rlo = (uint32_t)(t >> 7);               // 0..3
        s_eu[t]       = dsmem_read_f32(a_eul + off, rlo);
        s_eu[t + 512] = dsmem_read_f32(a_eul + off, rlo + 4u);
        s_ev[t]       = dsmem_read_f32(a_evl + off, rlo);
        s_ev[t + 512] = dsmem_read_f32(a_evl + off, rlo + 4u);
    }
    __syncthreads();

    // Signal: this CTA is done reading peer smem. (Matching wait at the end
    // keeps every CTA's smem alive until all peers finish their reads.)
    cluster_arrive();

    // ---- Phase C: adj[i,j] = 0.5*(1/(1+eu_i*ev_j) + 1/(1+eu_j*ev_i)) ----
    // This CTA writes 8 global rows; 512 threads = 2 rows per sweep x 256 float4 cols.
    {
        const int colg    = t & 255;
        const int row_sub = t >> 8;
        const float4 euj = reinterpret_cast<const float4*>(s_eu)[colg];
        const float4 evj = reinterpret_cast<const float4*>(s_ev)[colg];
#pragma unroll
        for (int rr = 0; rr < 4; rr++) {
            const int i = blockIdx.x * 8 + rr * 2 + row_sub;
            const float eui = s_eu[i];
            const float evi = s_ev[i];
            float4 o;
            o.x = 0.5f * (frcp(fmaf(eui, evj.x, 1.f)) + frcp(fmaf(euj.x, evi, 1.f)));
            o.y = 0.5f * (frcp(fmaf(eui, evj.y, 1.f)) + frcp(fmaf(euj.y, evi, 1.f)));
            o.z = 0.5f * (frcp(fmaf(eui, evj.z, 1.f)) + frcp(fmaf(euj.z, evi, 1.f)));
            o.w = 0.5f * (frcp(fmaf(eui, evj.w, 1.f)) + frcp(fmaf(euj.w, evi, 1.f)));
            reinterpret_cast<float4*>(out)[(size_t)i * (NN / 4) + colg] = o;
        }
    }

    cluster_wait();   // all peers finished DSMEM reads; safe to exit
}

extern "C" void kernel_launch(void* const* d_in, const int* in_sizes, int n_in,
                              void* d_out, int out_size) {
    const float* z  = (const float*)d_in[0];  // [N, D]
    const float* w1 = (const float*)d_in[1];  // [2D, H]
    const float* b1 = (const float*)d_in[2];  // [H]
    const float* w2 = (const float*)d_in[3];  // [H]
    const float* b2 = (const float*)d_in[4];  // [1]
    float* out = (float*)d_out;               // [N, N]

    fused_decoder<<<NBLK, NTHR>>>(z, w1, b1, w2, b2, out);
}

// round 7
// speedup vs baseline: 1.5923x; 1.5923x over previous
#include <cuda_runtime.h>
#include <cstdint>

// Shapes fixed by problem: N=1024 nodes, D=256 feat, H=256 hidden.
#define NN 1024
#define DD 256
#define HH 256
#define NBLK 128          // <= 148 SMs, 1 CTA/SM -> all co-resident -> device barrier safe
#define NTHR 512          // 16 warps/block

// Scratch (__device__ globals: allocation-free rule)
__device__ float g_p[DD];     // w1[:D] @ w2
__device__ float g_q[DD];     // w1[D:] @ w2
__device__ float g_c;         // b1.w2 + b2
__device__ float g_eu[NN];    // exp(-(u_i + c))
__device__ float g_ev[NN];    // exp(-v_i)

__device__ unsigned g_cnt = 0;   // resets to 0 before each release
__device__ unsigned g_gen = 0;   // monotonically increments (wrap-safe inequality test)

__device__ __forceinline__ float warp_reduce(float v) {
#pragma unroll
    for (int o = 16; o > 0; o >>= 1) v += __shfl_xor_sync(0xffffffffu, v, o);
    return v;
}

__device__ __forceinline__ float frcp(float x) {
    float y;
    asm("rcp.approx.f32 %0, %1;" : "=f"(y) : "f"(x));
    return y;
}

__device__ __forceinline__ unsigned ld_acquire(unsigned* p) {
    unsigned v;
    asm volatile("ld.global.acquire.gpu.u32 %0, [%1];" : "=r"(v) : "l"(p) : "memory");
    return v;
}
__device__ __forceinline__ unsigned atom_add_release(unsigned* p, unsigned a) {
    unsigned v;
    asm volatile("atom.global.add.release.gpu.u32 %0, [%1], %2;" : "=r"(v) : "l"(p), "r"(a) : "memory");
    return v;
}
__device__ __forceinline__ void st_relaxed(unsigned* p, unsigned v) {
    asm volatile("st.global.relaxed.gpu.u32 [%0], %1;" :: "l"(p), "r"(v) : "memory");
}

// Flat grid barrier with acquire/release semantics (no MEMBAR.GL on fast path).
// All NBLK CTAs co-resident (1 CTA/SM), so spinning is deadlock-free.
__device__ __forceinline__ void grid_barrier() {
    __syncthreads();
    if (threadIdx.x == 0) {
        unsigned gen = ld_acquire(&g_gen);                    // capture BEFORE arrival
        unsigned t = atom_add_release(&g_cnt, 1u);            // releases this block's writes
        if (t == NBLK - 1u) {
            st_relaxed(&g_cnt, 0u);                           // reset (ordered by release below)
            atom_add_release(&g_gen, 1u);                     // release crossing
        } else {
            while (ld_acquire(&g_gen) == gen) { }             // acquire others' writes
        }
    }
    __syncthreads();
}

__global__ void __launch_bounds__(NTHR, 1)
fused_decoder(const float* __restrict__ z,  const float* __restrict__ w1,
              const float* __restrict__ b1, const float* __restrict__ w2,
              const float* __restrict__ b2, float* __restrict__ out) {
    const int lane  = threadIdx.x & 31;
    const int wid   = threadIdx.x >> 5;                       // 0..15
    const int gwarp = blockIdx.x * (NTHR / 32) + wid;         // 0..2047

    // ---- Prefetch phase-B inputs (z row) BEFORE the first barrier: these
    //      loads do not depend on p/q, so their latency overlaps barrier wait.
    float4 z0 = make_float4(0.f, 0.f, 0.f, 0.f);
    float4 z1 = z0;
    if (gwarp < NN) {
        const float4* zrow = reinterpret_cast<const float4*>(z + (size_t)gwarp * DD);
        z0 = zrow[lane];
        z1 = zrow[lane + 32];
    }

    // ---- Phase A: p = w1_top@w2, q = w1_bot@w2, c = b1.w2 + b2 ----
    if (gwarp <= 2 * DD) {
        const float4* w2v = reinterpret_cast<const float4*>(w2);
        const float4 a0 = w2v[lane];
        const float4 a1 = w2v[lane + 32];
        const float4* row = (gwarp < 2 * DD)
            ? reinterpret_cast<const float4*>(w1 + (size_t)gwarp * HH)
            : reinterpret_cast<const float4*>(b1);
        float4 r0 = row[lane];
        float4 r1 = row[lane + 32];
        float acc = r0.x * a0.x;
        acc = fmaf(r0.y, a0.y, acc);
        acc = fmaf(r0.z, a0.z, acc);
        acc = fmaf(r0.w, a0.w, acc);
        acc = fmaf(r1.x, a1.x, acc);
        acc = fmaf(r1.y, a1.y, acc);
        acc = fmaf(r1.z, a1.z, acc);
        acc = fmaf(r1.w, a1.w, acc);
        acc = warp_reduce(acc);
        if (lane == 0) {
            if (gwarp < DD)           g_p[gwarp] = acc;
            else if (gwarp < 2 * DD)  g_q[gwarp - DD] = acc;
            else                      g_c = acc + b2[0];
        }
    }

    grid_barrier();

    // ---- Phase B: eu_i = exp(-(z_i.p + c)), ev_i = exp(-(z_i.q)) ----
    if (gwarp < NN) {
        const float4* pv = reinterpret_cast<const float4*>(g_p);
        const float4* qv = reinterpret_cast<const float4*>(g_q);
        float4 p0 = pv[lane], p1 = pv[lane + 32];
        float4 q0 = qv[lane], q1 = qv[lane + 32];
        float su = z0.x * p0.x;
        su = fmaf(z0.y, p0.y, su);
        su = fmaf(z0.z, p0.z, su);
        su = fmaf(z0.w, p0.w, su);
        su = fmaf(z1.x, p1.x, su);
        su = fmaf(z1.y, p1.y, su);
        su = fmaf(z1.z, p1.z, su);
        su = fmaf(z1.w, p1.w, su);
        float sv = z0.x * q0.x;
        sv = fmaf(z0.y, q0.y, sv);
        sv = fmaf(z0.z, q0.z, sv);
        sv = fmaf(z0.w, q0.w, sv);
        sv = fmaf(z1.x, q1.x, sv);
        sv = fmaf(z1.y, q1.y, sv);
        sv = fmaf(z1.z, q1.z, sv);
        sv = fmaf(z1.w, q1.w, sv);
        su = warp_reduce(su);
        sv = warp_reduce(sv);
        if (lane == 0) {
            g_eu[gwarp] = __expf(-(su + g_c));
            g_ev[gwarp] = __expf(-sv);
        }
    }

    grid_barrier();

    // ---- Phase C: adj[i,j] = 0.5*(1/(1+eu_i*ev_j) + 1/(1+eu_j*ev_i)) ----
    // Block covers 8 rows; 512 threads = 2 rows per sweep x 256 float4 cols.
    const int colg    = threadIdx.x & 255;      // float4 column group 0..255
    const int row_sub = threadIdx.x >> 8;       // 0..1
    const int j = colg * 4;
    const float4 euj = *reinterpret_cast<const float4*>(g_eu + j);
    const float4 evj = *reinterpret_cast<const float4*>(g_ev + j);
#pragma unroll
    for (int rr = 0; rr < 4; rr++) {
        const int i = blockIdx.x * 8 + rr * 2 + row_sub;
        const float eui = g_eu[i];
        const float evi = g_ev[i];
        float4 o;
        o.x = 0.5f * (frcp(fmaf(eui, evj.x, 1.f)) + frcp(fmaf(euj.x, evi, 1.f)));
        o.y = 0.5f * (frcp(fmaf(eui, evj.y, 1.f)) + frcp(fmaf(euj.y, evi, 1.f)));
        o.z = 0.5f * (frcp(fmaf(eui, evj.z, 1.f)) + frcp(fmaf(euj.z, evi, 1.f)));
        o.w = 0.5f * (frcp(fmaf(eui, evj.w, 1.f)) + frcp(fmaf(euj.w, evi, 1.f)));
        reinterpret_cast<float4*>(out)[(size_t)i * (NN / 4) + colg] = o;
    }
}

extern "C" void kernel_launch(void* const* d_in, const int* in_sizes, int n_in,
                              void* d_out, int out_size) {
    const float* z  = (const float*)d_in[0];  // [N, D]
    const float* w1 = (const float*)d_in[1];  // [2D, H]
    const float* b1 = (const float*)d_in[2];  // [H]
    const float* w2 = (const float*)d_in[3];  // [H]
    const float* b2 = (const float*)d_in[4];  // [1]
    float* out = (float*)d_out;               // [N, N]

    fused_decoder<<<NBLK, NTHR>>>(z, w1, b1, w2, b2, out);
}